// round 17
// baseline (speedup 1.0000x reference)
#include <cuda_runtime.h>
#include <cuda_bf16.h>
#include <math.h>
#include <stdint.h>

#define B_   64
#define S_   512
#define H_   1024
#define BH_  (B_ * H_)          // 65536
#define R_   (S_ * B_)          // 32768 time-major rows
#define NCTA 128

// ---------------- device scratch (no allocations allowed) ----------------
__device__ float          g_xi[(size_t)R_ * H_];     // 128 MB, time-major (s,b,h)
__device__ __nv_bfloat16  g_xhi[(size_t)R_ * H_];    // 64 MB split x (time-major)
__device__ __nv_bfloat16  g_xlo[(size_t)R_ * H_];    // 64 MB
__device__ __nv_bfloat16  g_whi[(size_t)H_ * H_];    // 2 MB split W_ih
__device__ __nv_bfloat16  g_wlo[(size_t)H_ * H_];    // 2 MB
__device__ __nv_bfloat16  g_hh[2][2][BH_];           // h split, [parity][hi/lo]
__device__ unsigned       g_hflag[4][32];            // h-ready, [bt][jt], single writer

__global__ void init_flags_kernel() {
    ((unsigned*)g_hflag)[threadIdx.x] = 0u;          // 128 threads
}

// ======================= helpers =======================
__device__ __forceinline__ uint32_t smem_u32(const void* p) {
    uint32_t a;
    asm("{ .reg .u64 t; cvta.to.shared.u64 t, %1; cvt.u32.u64 %0, t; }" : "=r"(a) : "l"(p));
    return a;
}

// fp32x4 -> (bf16 hi x4, bf16 lo x4), each packed as uint2 (mem order)
__device__ __forceinline__ void cvt_split4(float4 v, uint2& hi, uint2& lo) {
    uint32_t h0, h1, l0, l1;
    asm("cvt.rn.satfinite.bf16x2.f32 %0, %1, %2;" : "=r"(h0) : "f"(v.y), "f"(v.x));
    asm("cvt.rn.satfinite.bf16x2.f32 %0, %1, %2;" : "=r"(h1) : "f"(v.w), "f"(v.z));
    float r0 = v.x - __uint_as_float(h0 << 16);
    float r1 = v.y - __uint_as_float(h0 & 0xFFFF0000u);
    float r2 = v.z - __uint_as_float(h1 << 16);
    float r3 = v.w - __uint_as_float(h1 & 0xFFFF0000u);
    asm("cvt.rn.satfinite.bf16x2.f32 %0, %1, %2;" : "=r"(l0) : "f"(r1), "f"(r0));
    asm("cvt.rn.satfinite.bf16x2.f32 %0, %1, %2;" : "=r"(l1) : "f"(r3), "f"(r2));
    hi = make_uint2(h0, h1);
    lo = make_uint2(l0, l1);
}

#define LDMX4(r0, r1, r2, r3, addr) \
    asm volatile("ldmatrix.sync.aligned.m8n8.x4.shared.b16 {%0,%1,%2,%3}, [%4];" \
        : "=r"(r0), "=r"(r1), "=r"(r2), "=r"(r3) : "r"(addr))

#define MMA_BF16(c, a0, a1, a2, a3, b0, b1) \
    asm volatile("mma.sync.aligned.m16n8k16.row.col.f32.bf16.bf16.f32 " \
        "{%0,%1,%2,%3}, {%4,%5,%6,%7}, {%8,%9}, {%0,%1,%2,%3};" \
        : "+f"((c)[0]), "+f"((c)[1]), "+f"((c)[2]), "+f"((c)[3]) \
        : "r"(a0), "r"(a1), "r"(a2), "r"(a3), "r"(b0), "r"(b1))

#define CP_ASYNC16(saddr, gptr) \
    asm volatile("cp.async.cg.shared.global [%0], [%1], 16;" \
        :: "r"((uint32_t)(saddr)), "l"(gptr))
#define CP_COMMIT() asm volatile("cp.async.commit_group;" ::: "memory")
#define CP_WAIT(n)  asm volatile("cp.async.wait_group %0;" :: "n"(n) : "memory")

// =========================================================================
// Pre-pass kernels: one-time fp32 -> bf16 hi/lo split.
// =========================================================================
__global__ __launch_bounds__(256) void split_x_kernel(const float* __restrict__ x) {
    const int row_in = blockIdx.x;                   // b*512 + s
    const int b = row_in >> 9, s = row_in & 511;
    const size_t r_out = (size_t)(s * 64 + b);
    const int k4 = threadIdx.x * 4;
    const float4 v = *(const float4*)(x + (size_t)row_in * H_ + k4);
    uint2 h, l;
    cvt_split4(v, h, l);
    *(uint2*)(g_xhi + r_out * H_ + k4) = h;
    *(uint2*)(g_xlo + r_out * H_ + k4) = l;
}

__global__ __launch_bounds__(256) void split_w_kernel(const float* __restrict__ Wih) {
    const size_t row = blockIdx.x;
    const int k4 = threadIdx.x * 4;
    const float4 v = *(const float4*)(Wih + row * H_ + k4);
    uint2 h, l;
    cvt_split4(v, h, l);
    *(uint2*)(g_whi + row * H_ + k4) = h;
    *(uint2*)(g_wlo + row * H_ + k4) = l;
}

// =========================================================================
// Kernel 1 (HMMA): xi GEMM with cp.async double-buffered staging.
// Grid (8 jt, 256 rt). CTA tile 128x128, K-chunk 64.
// C = Ahi*Whi + Ahi*Wlo + Alo*Whi, fp32 accumulation.
// =========================================================================
#define KC        64
#define LDSTR     72
#define TILE_ELM  (128 * LDSTR)
#define BUF_BYTES (4 * TILE_ELM * 2)          // 73728
#define GEMM_SMEM (2 * BUF_BYTES)             // 147456

__global__ __launch_bounds__(256) void gemm_xi_mma(const float* __restrict__ bih)
{
    extern __shared__ __nv_bfloat16 smb[];
    const uint32_t smb0 = smem_u32(smb);

    const int t      = threadIdx.x;
    const int lane   = t & 31;
    const int wid    = t >> 5;
    const int warp_m = wid >> 2;
    const int warp_n = wid & 3;
    const int jt = blockIdx.x;
    const int rt = blockIdx.y;
    const int r0 = rt * 128;
    const int j0 = jt * 128;

    float acc[4][4][4];
#pragma unroll
    for (int mi = 0; mi < 4; mi++)
#pragma unroll
        for (int ni = 0; ni < 4; ni++)
#pragma unroll
            for (int q = 0; q < 4; q++) acc[mi][ni][q] = 0.f;

    const int a_row = lane & 15;
    const int a_kof = ((lane >> 4) & 1) * 8;
    const int b_row = (lane & 7) + ((lane >> 4) & 1) * 8;
    const int b_kof = ((lane >> 3) & 1) * 8;

    // stage chunk kb into buffer buf via cp.async (16 x 16B per thread)
    auto issue_stage = [&](int kb, int buf) {
        const int k0 = kb * KC;
        const uint32_t base = smb0 + (uint32_t)buf * BUF_BYTES;
#pragma unroll
        for (int i = 0; i < 16; i++) {
            const int f    = t + 256 * i;    // 0..4095 uint4 slots
            const int tile = f >> 10;        // 0..3
            const int g    = f & 1023;
            const int row  = g >> 3;         // 0..127
            const int k8   = (g & 7) * 8;    // 0..56
            const __nv_bfloat16* src =
                (tile == 0) ? g_xhi : (tile == 1) ? g_xlo : (tile == 2) ? g_whi : g_wlo;
            const size_t grow = (size_t)((tile < 2 ? r0 : j0) + row);
            CP_ASYNC16(base + (uint32_t)(tile * TILE_ELM + row * LDSTR + k8) * 2,
                       src + grow * H_ + k0 + k8);
        }
        CP_COMMIT();
    };

    issue_stage(0, 0);

    for (int kb = 0; kb < 16; kb++) {
        if (kb + 1 < 16) {
            issue_stage(kb + 1, (kb + 1) & 1);
            CP_WAIT(1);
        } else {
            CP_WAIT(0);
        }
        __syncthreads();

        const uint32_t bb  = smb0 + (uint32_t)(kb & 1) * BUF_BYTES;
        const uint32_t ahi = bb;
        const uint32_t alo = bb + TILE_ELM * 2;
        const uint32_t bhi = bb + 2 * TILE_ELM * 2;
        const uint32_t blo = bb + 3 * TILE_ELM * 2;

#pragma unroll
        for (int kk = 0; kk < KC; kk += 16) {
            uint32_t bh[8], bl[8];
#pragma unroll
            for (int p = 0; p < 2; p++) {
                const int n0 = warp_n * 32 + p * 16;
                const uint32_t off = (uint32_t)(((n0 + b_row) * LDSTR + kk + b_kof) * 2);
                LDMX4(bh[p*4+0], bh[p*4+1], bh[p*4+2], bh[p*4+3], bhi + off);
                LDMX4(bl[p*4+0], bl[p*4+1], bl[p*4+2], bl[p*4+3], blo + off);
            }
#pragma unroll
            for (int mi = 0; mi < 4; mi++) {
                const int m0 = warp_m * 64 + mi * 16;
                const uint32_t off = (uint32_t)(((m0 + a_row) * LDSTR + kk + a_kof) * 2);
                uint32_t ah0, ah1, ah2, ah3, al0, al1, al2, al3;
                LDMX4(ah0, ah1, ah2, ah3, ahi + off);
                LDMX4(al0, al1, al2, al3, alo + off);
#pragma unroll
                for (int ni = 0; ni < 4; ni++) {
                    MMA_BF16(acc[mi][ni], ah0, ah1, ah2, ah3, bh[ni*2+0], bh[ni*2+1]);
                    MMA_BF16(acc[mi][ni], ah0, ah1, ah2, ah3, bl[ni*2+0], bl[ni*2+1]);
                    MMA_BF16(acc[mi][ni], al0, al1, al2, al3, bh[ni*2+0], bh[ni*2+1]);
                }
            }
        }
        __syncthreads();
    }

    const int gr = lane >> 2;
    const int gc = (lane & 3) * 2;
#pragma unroll
    for (int ni = 0; ni < 4; ni++) {
        const int col = j0 + warp_n * 32 + ni * 8 + gc;
        const float bia0 = __ldg(bih + col);
        const float bia1 = __ldg(bih + col + 1);
#pragma unroll
        for (int mi = 0; mi < 4; mi++) {
            const int row = r0 + warp_m * 64 + mi * 16 + gr;
            float2 v0, v1;
            v0.x = acc[mi][ni][0] + bia0;
            v0.y = acc[mi][ni][1] + bia1;
            v1.x = acc[mi][ni][2] + bia0;
            v1.y = acc[mi][ni][3] + bia1;
            *(float2*)(g_xi + (size_t)row * H_ + col)       = v0;
            *(float2*)(g_xi + (size_t)(row + 8) * H_ + col) = v1;
        }
    }
}

// =========================================================================
// Persistent recurrence, full-K per CTA, warp-granular flag gating.
// 128 CTAs = 32 jt x 4 bt. Per-(bt,jt) flag, single writer (release store);
// consumer warp w polls only its 4 producers (jt = 4w..4w+3) with acquire.
// =========================================================================
#define WJ_   32                              // j cols per CTA
#define WB_   16                              // b rows per CTA
#define WSTR  1032                            // W row stride (1024 + 8)
#define HSTR  136                             // h row stride per warp (128 + 8)
#define SM_WH 0
#define SM_WL (WJ_ * WSTR)
#define SM_HH (2 * WJ_ * WSTR)
#define SM_HL (SM_HH + 8 * WB_ * HSTR)
#define SM_ELEMS (SM_HL + 8 * WB_ * HSTR)
#define RED_OFF  (SM_ELEMS * 2)
#define REDSTR   34
#define RNN_SMEM (RED_OFF + 8 * WB_ * REDSTR * 4)  // 219136 B

__global__ __launch_bounds__(256, 1) void rnn_kernel(
    const float* __restrict__ Whh,
    const float* __restrict__ bhh,
    float* __restrict__ out)                   // d_out: (S,B,H) then h_final
{
    extern __shared__ __nv_bfloat16 smr[];
    __nv_bfloat16* Wh = smr + SM_WH;
    __nv_bfloat16* Wl = smr + SM_WL;
    __nv_bfloat16* Hh = smr + SM_HH;           // [8 warps][16][HSTR]
    __nv_bfloat16* Hl = smr + SM_HL;
    float* red = (float*)((char*)smr + RED_OFF);   // [8][16][REDSTR]

    const uint32_t wh_a = smem_u32(Wh);
    const uint32_t wl_a = smem_u32(Wl);
    const uint32_t hh_a = smem_u32(Hh);
    const uint32_t hl_a = smem_u32(Hl);

    const int t    = threadIdx.x;
    const int lane = t & 31;
    const int w    = t >> 5;                   // warp id = k-slice
    const int cta  = blockIdx.x;
    const int jt   = cta >> 2;                 // 0..31 (32 j cols)
    const int bt   = cta & 3;                  // 0..3  (16 b rows)
    const int j0   = jt * WJ_;
    const int bg0  = bt * WB_;

    const int a_row = lane & 15;
    const int a_kof = ((lane >> 4) & 1) * 8;
    const int b_row = (lane & 7) + ((lane >> 4) & 1) * 8;
    const int b_kof = ((lane >> 3) & 1) * 8;
    const uint32_t hh_w = hh_a + (uint32_t)(w * WB_ * HSTR) * 2;
    const uint32_t hl_w = hl_a + (uint32_t)(w * WB_ * HSTR) * 2;

    // this warp's 4 producer flags (jt' = 4w + lane&3, same bt)
    unsigned* my_flag = &g_hflag[bt][4 * w + (lane & 3)];

    // reducer constants
    const int rb   = t >> 4;                   // 0..15
    const int rcol = (t & 15) * 2;             // 0..30
    const size_t oidx = ((size_t)(bg0 + rb) << 10) + j0 + rcol;
    const float bh0 = bhh[j0 + rcol];
    const float bh1 = bhh[j0 + rcol + 1];

    // ---- one-time: split W_hh tile (32 j x 1024 k) into SMEM hi/lo ----
#pragma unroll
    for (int i = 0; i < 32; i++) {
        const int f   = t + 256 * i;
        const int row = f >> 8;                // 0..31 (j-local)
        const int k4  = (f & 255) * 4;         // 0..1020
        const float4 v = *(const float4*)(Whh + (size_t)(j0 + row) * H_ + k4);
        uint2 h, l;
        cvt_split4(v, h, l);
        *(uint2*)(Wh + row * WSTR + k4) = h;
        *(uint2*)(Wl + row * WSTR + k4) = l;
    }
    __syncthreads();

    for (int s = 0; s < S_; s++) {
        // ---- prefetch xi(s) block (independent of gate) ----
        const float2 xi2 = *(const float2*)(g_xi + (size_t)s * BH_ + oidx);

        // ---- warp-level gate (4 producers) + private stage of h(s-1) ----
        if (s == 0) {
#pragma unroll
            for (int i = 0; i < 8; i++) {
                const int f   = lane + 32 * i;
                const int row = f >> 4;
                const int k8  = (f & 15) * 8;
                *(uint4*)(Hh + w * WB_ * HSTR + row * HSTR + k8) = make_uint4(0, 0, 0, 0);
                *(uint4*)(Hl + w * WB_ * HSTR + row * HSTR + k8) = make_uint4(0, 0, 0, 0);
            }
            __syncwarp();
        } else {
            const unsigned tgt = (unsigned)s;
            unsigned v;
            do {
                asm volatile("ld.acquire.gpu.global.b32 %0, [%1];"
                             : "=r"(v) : "l"(my_flag) : "memory");
            } while (__any_sync(0xFFFFFFFFu, v < tgt));
            const __nv_bfloat16* shi = g_hh[(s + 1) & 1][0];
            const __nv_bfloat16* slo = g_hh[(s + 1) & 1][1];
#pragma unroll
            for (int i = 0; i < 8; i++) {
                const int f   = lane + 32 * i;   // 0..255 uint4 slots
                const int row = f >> 4;          // 0..15 (b-local)
                const int k8  = (f & 15) * 8;    // 0..120
                const size_t gsrc = ((size_t)(bg0 + row) << 10) + w * 128 + k8;
                *(uint4*)(Hh + w * WB_ * HSTR + row * HSTR + k8) = *(const uint4*)(shi + gsrc);
                *(uint4*)(Hl + w * WB_ * HSTR + row * HSTR + k8) = *(const uint4*)(slo + gsrc);
            }
            __syncwarp();
        }

        // ---- m16 n32 k128 x 3-term split HMMA (warp-private k-slice) ----
        float acc[4][4];
#pragma unroll
        for (int ni = 0; ni < 4; ni++)
#pragma unroll
            for (int q = 0; q < 4; q++) acc[ni][q] = 0.f;

#pragma unroll
        for (int kk = 0; kk < 128; kk += 16) {
            const int wk = w * 128 + kk;
            uint32_t ah0, ah1, ah2, ah3, al0, al1, al2, al3;
            {
                const uint32_t off = (uint32_t)((a_row * HSTR + kk + a_kof) * 2);
                LDMX4(ah0, ah1, ah2, ah3, hh_w + off);
                LDMX4(al0, al1, al2, al3, hl_w + off);
            }
            uint32_t bh[8], bl[8];
#pragma unroll
            for (int p = 0; p < 2; p++) {
                const uint32_t off = (uint32_t)(((p * 16 + b_row) * WSTR + wk + b_kof) * 2);
                LDMX4(bh[p*4+0], bh[p*4+1], bh[p*4+2], bh[p*4+3], wh_a + off);
                LDMX4(bl[p*4+0], bl[p*4+1], bl[p*4+2], bl[p*4+3], wl_a + off);
            }
#pragma unroll
            for (int ni = 0; ni < 4; ni++) {
                MMA_BF16(acc[ni], ah0, ah1, ah2, ah3, bh[ni*2+0], bh[ni*2+1]);
                MMA_BF16(acc[ni], ah0, ah1, ah2, ah3, bl[ni*2+0], bl[ni*2+1]);
                MMA_BF16(acc[ni], al0, al1, al2, al3, bh[ni*2+0], bh[ni*2+1]);
            }
        }

        // ---- deposit warp partial (16x32) in SMEM ----
        {
            const int gr = lane >> 2;
            const int gc = (lane & 3) * 2;
            float* rw = red + w * WB_ * REDSTR;
#pragma unroll
            for (int ni = 0; ni < 4; ni++) {
                float2 v0, v1;
                v0.x = acc[ni][0]; v0.y = acc[ni][1];
                v1.x = acc[ni][2]; v1.y = acc[ni][3];
                *(float2*)&rw[gr * REDSTR + ni * 8 + gc]       = v0;
                *(float2*)&rw[(gr + 8) * REDSTR + ni * 8 + gc] = v1;
            }
        }
        __syncthreads();

        // ---- block reduce over 8 warps + xi + bias -> tanh -> h ----
        {
            float v0 = xi2.x + bh0;
            float v1 = xi2.y + bh1;
#pragma unroll
            for (int q = 0; q < 8; q++) {
                const float2 p = *(const float2*)&red[(q * WB_ + rb) * REDSTR + rcol];
                v0 += p.x; v1 += p.y;
            }
            const float h0 = tanhf(v0);
            const float h1 = tanhf(v1);
            float2 ho; ho.x = h0; ho.y = h1;
            *(float2*)(out + (size_t)s * BH_ + oidx) = ho;
            __nv_bfloat162 hb;
            hb.x = __float2bfloat16_rn(h0);
            hb.y = __float2bfloat16_rn(h1);
            *(__nv_bfloat162*)(g_hh[s & 1][0] + oidx) = hb;
            __nv_bfloat162 lb;
            lb.x = __float2bfloat16_rn(h0 - __bfloat162float(hb.x));
            lb.y = __float2bfloat16_rn(h1 - __bfloat162float(hb.y));
            *(__nv_bfloat162*)(g_hh[s & 1][1] + oidx) = lb;
            if (s == S_ - 1)
                *(float2*)(out + (size_t)S_ * BH_ + oidx) = ho;
        }

        // ---- publish h block: single-writer release store (no atomic) ----
        __syncthreads();
        if (t == 0) {
            asm volatile("st.release.gpu.global.b32 [%0], %1;"
                         :: "l"(&g_hflag[bt][jt]), "r"((unsigned)(s + 1)) : "memory");
        }
    }
}

// =========================================================================
extern "C" void kernel_launch(void* const* d_in, const int* in_sizes, int n_in,
                              void* d_out, int out_size)
{
    (void)in_sizes; (void)n_in; (void)out_size;
    const float* x   = (const float*)d_in[0];
    const float* Wih = (const float*)d_in[1];
    const float* bih = (const float*)d_in[2];
    const float* Whh = (const float*)d_in[3];
    const float* bhh = (const float*)d_in[4];
    float* out = (float*)d_out;

    cudaFuncSetAttribute(rnn_kernel,  cudaFuncAttributeMaxDynamicSharedMemorySize, RNN_SMEM);
    cudaFuncSetAttribute(gemm_xi_mma, cudaFuncAttributeMaxDynamicSharedMemorySize, GEMM_SMEM);

    init_flags_kernel<<<1, 128>>>();
    split_x_kernel<<<R_, 256>>>(x);
    split_w_kernel<<<H_, 256>>>(Wih);
    gemm_xi_mma<<<dim3(8, 256, 1), 256, GEMM_SMEM>>>(bih);
    rnn_kernel<<<NCTA, 256, RNN_SMEM>>>(Whh, bhh, out);
}